// round 8
// baseline (speedup 1.0000x reference)
#include <cuda_runtime.h>
#include <math.h>
#include <stdint.h>

#define T_  2048
#define D_  1024
#define I_  512
#define E_  32
#define K_  6
#define SI_ 1024

#define BM 64
#define BN 128
#define BK 32
#define ASTR 36      // A smem row stride (words): conflict-free frag loads
#define BSTR 136     // B smem row stride (words): conflict-free frag loads
#define AWORDS (BM * ASTR)       // 2304
#define BWORDS (BK * BSTR)       // 4352
#define ABYTES (AWORDS * 4)      // 9216
#define BBYTES (BWORDS * 4)      // 17408

// 3-stage layouts (bytes):
//   dual:   A[3]@0 (27648), B1[3]@27648 (52224), B2[3]@79872 (52224), slots@132096
//   single: A[3]@0 (27648), B[3]@27648 (52224), slots@79872
#define DUAL_SMEM   (132096 + 256)
#define SINGLE_SMEM (79872 + 256)

// ---------------- scratch (no allocations allowed) ----------------
__device__ float g_w1t[E_ * D_ * I_];     // tf32-rounded weights, original layout
__device__ float g_w2t[E_ * D_ * I_];
__device__ float g_w3t[E_ * I_ * D_];
__device__ float g_sw1t[D_ * SI_];
__device__ float g_sw2t[D_ * SI_];
__device__ float g_sw3t[SI_ * D_];
__device__ float g_xtf[T_ * D_];
__device__ float g_zh[T_ * SI_];
__device__ float g_hs[T_ * K_ * I_];
__device__ int   g_cnt[E_];
__device__ int   g_slots[E_ * T_];
__device__ int   g_tidx[T_ * K_];
__device__ float g_tval[T_ * K_];

__device__ __forceinline__ unsigned f2tf(float f) {
    unsigned u;
    asm("cvt.rna.tf32.f32 %0, %1;" : "=r"(u) : "f"(f));
    return u;
}
__device__ __forceinline__ void cpa16(unsigned dst, const float* src) {
    asm volatile("cp.async.cg.shared.global [%0], [%1], 16;" :: "r"(dst), "l"(src));
}
#define CP_COMMIT asm volatile("cp.async.commit_group;")
#define CP_WAIT1  asm volatile("cp.async.wait_group 1;")
#define CP_WAIT0  asm volatile("cp.async.wait_group 0;")

#define MMA8(c, a, b0v, b1v) \
    asm volatile("mma.sync.aligned.m16n8k8.row.col.f32.tf32.tf32.f32 " \
        "{%0,%1,%2,%3},{%4,%5,%6,%7},{%8,%9},{%0,%1,%2,%3};" \
        : "+f"((c)[0]), "+f"((c)[1]), "+f"((c)[2]), "+f"((c)[3]) \
        : "r"((a)[0]), "r"((a)[1]), "r"((a)[2]), "r"((a)[3]), "r"(b0v), "r"(b1v))

// ---------------- init ----------------
__global__ void moe_init_kernel() {
    if (threadIdx.x < E_) g_cnt[threadIdx.x] = 0;
}

// ---------------- convert weights + x to RNA-rounded tf32 bits ----------------
__global__ __launch_bounds__(256) void moe_cvt_kernel(
    const float* __restrict__ W1, const float* __restrict__ W2, const float* __restrict__ W3,
    const float* __restrict__ sw1, const float* __restrict__ sw2, const float* __restrict__ sw3,
    const float* __restrict__ x)
{
    const long NW = (long)E_ * D_ * I_ / 4;
    const long NS = (long)D_ * SI_ / 4;
    const long NX = (long)T_ * D_ / 4;
    long i = (long)blockIdx.x * 256 + threadIdx.x;
    const float4* s; float4* d;
    if (i < NW)                     { s = (const float4*)W1  + i;                 d = (float4*)g_w1t  + i; }
    else if (i < 2*NW)              { s = (const float4*)W2  + (i - NW);          d = (float4*)g_w2t  + (i - NW); }
    else if (i < 3*NW)              { s = (const float4*)W3  + (i - 2*NW);        d = (float4*)g_w3t  + (i - 2*NW); }
    else if (i < 3*NW + NS)         { s = (const float4*)sw1 + (i - 3*NW);        d = (float4*)g_sw1t + (i - 3*NW); }
    else if (i < 3*NW + 2*NS)       { s = (const float4*)sw2 + (i - 3*NW - NS);   d = (float4*)g_sw2t + (i - 3*NW - NS); }
    else if (i < 3*NW + 3*NS)       { s = (const float4*)sw3 + (i - 3*NW - 2*NS); d = (float4*)g_sw3t + (i - 3*NW - 2*NS); }
    else if (i < 3*NW + 3*NS + NX)  { s = (const float4*)x   + (i - 3*NW - 3*NS); d = (float4*)g_xtf  + (i - 3*NW - 3*NS); }
    else return;
    float4 v = *s;
    v.x = __uint_as_float(f2tf(v.x)); v.y = __uint_as_float(f2tf(v.y));
    v.z = __uint_as_float(f2tf(v.z)); v.w = __uint_as_float(f2tf(v.w));
    *d = v;
}
#define CVT_GRID 54272

// ---------------- router: 1 warp per token (validated) ----------------
__global__ __launch_bounds__(256) void moe_router_kernel(
    const float* __restrict__ x, const float* __restrict__ rw, const float* __restrict__ rb)
{
    __shared__ float sh[8][32];
    const int wi = threadIdx.x >> 5, lane = threadIdx.x & 31;
    const int t = blockIdx.x * 8 + wi;

    const float4* xr = (const float4*)(x + (size_t)t * D_);
    float4 xv[8];
    #pragma unroll
    for (int d = 0; d < 8; d++) xv[d] = xr[d * 32 + lane];

    for (int e = 0; e < E_; e += 2) {
        const float4* w0 = (const float4*)(rw + (size_t)e * D_);
        const float4* w1 = (const float4*)(rw + (size_t)(e + 1) * D_);
        float acc0 = 0.f, acc1 = 0.f;
        #pragma unroll
        for (int d = 0; d < 8; d++) {
            float4 b0 = w0[d * 32 + lane], b1 = w1[d * 32 + lane];
            acc0 += xv[d].x * b0.x + xv[d].y * b0.y + xv[d].z * b0.z + xv[d].w * b0.w;
            acc1 += xv[d].x * b1.x + xv[d].y * b1.y + xv[d].z * b1.z + xv[d].w * b1.w;
        }
        #pragma unroll
        for (int off = 16; off; off >>= 1) {
            acc0 += __shfl_down_sync(0xffffffffu, acc0, off);
            acc1 += __shfl_down_sync(0xffffffffu, acc1, off);
        }
        if (lane == 0) { sh[wi][e] = acc0 + rb[e]; sh[wi][e + 1] = acc1 + rb[e + 1]; }
    }
    __syncwarp();
    float logit = sh[wi][lane];

    float mx = logit;
    #pragma unroll
    for (int off = 16; off; off >>= 1)
        mx = fmaxf(mx, __shfl_xor_sync(0xffffffffu, mx, off));
    float p = expf(logit - mx);
    float sm = p;
    #pragma unroll
    for (int off = 16; off; off >>= 1)
        sm += __shfl_xor_sync(0xffffffffu, sm, off);
    float score = p / sm;

    const int grp = lane >> 2;
    float v0 = __shfl_sync(0xffffffffu, score, grp * 4 + 0);
    float v1 = __shfl_sync(0xffffffffu, score, grp * 4 + 1);
    float v2 = __shfl_sync(0xffffffffu, score, grp * 4 + 2);
    float v3 = __shfl_sync(0xffffffffu, score, grp * 4 + 3);
    float a = fmaxf(v0, v1), b = fminf(v0, v1);
    float c = fmaxf(v2, v3), dd = fminf(v2, v3);
    float top2 = (a >= c) ? (a + fmaxf(b, c)) : (c + fmaxf(a, dd));

    float gsa[8];
    #pragma unroll
    for (int j = 0; j < 8; j++) gsa[j] = __shfl_sync(0xffffffffu, top2, j * 4);
    unsigned keep = 0;
    #pragma unroll
    for (int it = 0; it < 4; it++) {
        float bv = -1e30f; int bj = 0;
        #pragma unroll
        for (int j = 0; j < 8; j++) {
            bool cand = (((keep >> j) & 1u) == 0u) && (gsa[j] > bv);
            if (cand) { bv = gsa[j]; bj = j; }
        }
        keep |= 1u << bj;
    }

    float msc = ((keep >> grp) & 1u) ? score : -1e30f;
    __syncwarp();
    sh[wi][lane] = msc;
    __syncwarp();

    if (lane == 0) {
        #pragma unroll
        for (int kk = 0; kk < K_; kk++) {
            float bv = -1e30f; int be = 0;
            for (int ee = 0; ee < 32; ee++) {
                float s = sh[wi][ee];
                if (s > bv) { bv = s; be = ee; }
            }
            sh[wi][be] = -2e30f;
            g_tidx[t * K_ + kk] = be;
            g_tval[t * K_ + kk] = bv;
            int pos = atomicAdd(&g_cnt[be], 1);
            g_slots[be * T_ + pos] = t * K_ + kk;
        }
    }
}

// ---------------- bias pre-pass: out[t] = sb3 + sum_k gate_k * b3[e_k] ----------------
__global__ __launch_bounds__(256) void moe_bias_kernel(
    const float* __restrict__ b3, const float* __restrict__ sb3, float* __restrict__ out)
{
    const int t = blockIdx.x;
    int ti[K_]; float tv[K_];
    #pragma unroll
    for (int k = 0; k < K_; k++) { ti[k] = g_tidx[t * K_ + k]; tv[k] = g_tval[t * K_ + k]; }
    for (int n = threadIdx.x * 4; n < D_; n += blockDim.x * 4) {
        float4 v = *(const float4*)(sb3 + n);
        #pragma unroll
        for (int k = 0; k < K_; k++) {
            float4 bb = *(const float4*)(b3 + (size_t)ti[k] * D_ + n);
            v.x = fmaf(tv[k], bb.x, v.x); v.y = fmaf(tv[k], bb.y, v.y);
            v.z = fmaf(tv[k], bb.z, v.z); v.w = fmaf(tv[k], bb.w, v.w);
        }
        *(float4*)(out + (size_t)t * D_ + n) = v;
    }
}

// ======================================================================
// cp.async tf32 GEMMs, BK=32, 3-buffer/2-in-flight pipeline, ONE sync/iter:
//   wait_group 1 -> sync -> prefetch(kt+2 -> slot (kt+2)%3) -> compute(slot kt%3)
// ======================================================================

#define A_COPY(dstbase, rowptr, k0) do { \
    cpa16((dstbase), (rowptr) + (k0) + ac * 4); \
    cpa16((dstbase) + 64, (rowptr) + (k0) + ac * 4 + 16); \
} while (0)
#define B_COPY(dstbase, gbase, ldb, k0) do { \
    _Pragma("unroll") \
    for (int j = 0; j < 4; j++) \
        cpa16((dstbase) + j * 128, (gbase) + (size_t)((k0) + bk) * (ldb) + bc * 4 + j * 32); \
} while (0)

#define WARP_IDS \
    const int lane = tid & 31, warp = tid >> 5; \
    const int wm = warp >> 2, wn = warp & 3; \
    const int grp = lane >> 2, tq = lane & 3; \
    const int mbase = wm * 32, nbase = wn * 32;

#define LOAD_AFRAGS(Ar) \
    unsigned a0[4], a1[4]; \
    { int r0 = mbase + grp; \
      a0[0] = (Ar)[r0 * ASTR + kq];     a0[1] = (Ar)[(r0 + 8) * ASTR + kq]; \
      a0[2] = (Ar)[r0 * ASTR + kq + 4]; a0[3] = (Ar)[(r0 + 8) * ASTR + kq + 4]; \
      int r1 = r0 + 16; \
      a1[0] = (Ar)[r1 * ASTR + kq];     a1[1] = (Ar)[(r1 + 8) * ASTR + kq]; \
      a1[2] = (Ar)[r1 * ASTR + kq + 4]; a1[3] = (Ar)[(r1 + 8) * ASTR + kq + 4]; }

// ---- shared stage 1 (dual B): g_zh = tf32(silu((x@sw1+sb1)*(x@sw2+sb2))) ----
__global__ __launch_bounds__(256, 1) void moe_shared_h_kernel(
    const float* __restrict__ sb1, const float* __restrict__ sb2)
{
    extern __shared__ __align__(16) char dsm[];
    const unsigned smb = (unsigned)__cvta_generic_to_shared(dsm);
    const int tid = threadIdx.x;
    const int mb = blockIdx.y * BM, nb = blockIdx.x * BN;
    const int am = tid >> 2, ac = tid & 3;
    const int bk = tid >> 3, bc = tid & 7;

    const float* aRow = g_xtf + (size_t)(mb + am) * D_;
    const float* B1g  = g_sw1t + nb;
    const float* B2g  = g_sw2t + nb;
    const unsigned aD  = smb + am * 144 + ac * 16;
    const unsigned b1D = smb + 27648 + bk * 544 + bc * 16;
    const unsigned b2D = smb + 79872 + bk * 544 + bc * 16;

    WARP_IDS;

    float c1[2][4][4] = {}, c2[2][4][4] = {};

    #pragma unroll
    for (int s = 0; s < 2; s++) {
        A_COPY(aD + s * ABYTES, aRow, s * BK);
        B_COPY(b1D + s * BBYTES, B1g, SI_, s * BK);
        B_COPY(b2D + s * BBYTES, B2g, SI_, s * BK);
        CP_COMMIT;
    }

    const int NT = D_ / BK;
    int scur = 0, spre = 2;
    #pragma unroll 1
    for (int kt = 0; kt < NT; kt++) {
        if (kt + 1 < NT) CP_WAIT1; else CP_WAIT0;
        __syncthreads();
        if (kt + 2 < NT) {
            const int k0 = (kt + 2) * BK;
            A_COPY(aD + spre * ABYTES, aRow, k0);
            B_COPY(b1D + spre * BBYTES, B1g, SI_, k0);
            B_COPY(b2D + spre * BBYTES, B2g, SI_, k0);
            CP_COMMIT;
        }
        const unsigned* Ar  = (const unsigned*)dsm + scur * AWORDS;
        const unsigned* B1r = (const unsigned*)dsm + 6912 + scur * BWORDS;
        const unsigned* B2r = (const unsigned*)dsm + 19968 + scur * BWORDS;
        #pragma unroll
        for (int ks = 0; ks < 4; ks++) {
            const int kq = ks * 8 + tq;
            LOAD_AFRAGS(Ar);
            #pragma unroll
            for (int in = 0; in < 4; in++) {
                int nc = nbase + in * 8 + grp;
                unsigned p0 = B1r[kq * BSTR + nc], p1 = B1r[(kq + 4) * BSTR + nc];
                unsigned q0 = B2r[kq * BSTR + nc], q1 = B2r[(kq + 4) * BSTR + nc];
                MMA8(c1[0][in], a0, p0, p1);
                MMA8(c1[1][in], a1, p0, p1);
                MMA8(c2[0][in], a0, q0, q1);
                MMA8(c2[1][in], a1, q0, q1);
            }
        }
        scur = (scur == 2) ? 0 : scur + 1;
        spre = (spre == 2) ? 0 : spre + 1;
    }

    #pragma unroll
    for (int im = 0; im < 2; im++)
        #pragma unroll
        for (int in = 0; in < 4; in++)
            #pragma unroll
            for (int r = 0; r < 4; r++) {
                int row = mb + mbase + im * 16 + grp + (r >= 2 ? 8 : 0);
                int col = nb + nbase + in * 8 + 2 * tq + (r & 1);
                float h1 = c1[im][in][r] + sb1[col];
                float h2 = c2[im][in][r] + sb2[col];
                float pp = h1 * h2;
                g_zh[(size_t)row * SI_ + col] = __uint_as_float(f2tf(pp / (1.f + expf(-pp))));
            }
}

// ---- shared stage 2: out += g_zh @ sw3 ----
__global__ __launch_bounds__(256, 2) void moe_out_init_kernel(float* __restrict__ out)
{
    extern __shared__ __align__(16) char dsm[];
    const unsigned smb = (unsigned)__cvta_generic_to_shared(dsm);
    const int tid = threadIdx.x;
    const int mb = blockIdx.y * BM, nb = blockIdx.x * BN;
    const int am = tid >> 2, ac = tid & 3;
    const int bk = tid >> 3, bc = tid & 7;

    const float* aRow = g_zh + (size_t)(mb + am) * SI_;
    const float* Bg   = g_sw3t + nb;
    const unsigned aD = smb + am * 144 + ac * 16;
    const unsigned bD = smb + 27648 + bk * 544 + bc * 16;

    WARP_IDS;

    float c[2][4][4] = {};

    #pragma unroll
    for (int s = 0; s < 2; s++) {
        A_COPY(aD + s * ABYTES, aRow, s * BK);
        B_COPY(bD + s * BBYTES, Bg, D_, s * BK);
        CP_COMMIT;
    }

    const int NT = SI_ / BK;
    int scur = 0, spre = 2;
    #pragma unroll 1
    for (int kt = 0; kt < NT; kt++) {
        if (kt + 1 < NT) CP_WAIT1; else CP_WAIT0;
        __syncthreads();
        if (kt + 2 < NT) {
            const int k0 = (kt + 2) * BK;
            A_COPY(aD + spre * ABYTES, aRow, k0);
            B_COPY(bD + spre * BBYTES, Bg, D_, k0);
            CP_COMMIT;
        }
        const unsigned* Ar = (const unsigned*)dsm + scur * AWORDS;
        const unsigned* Br = (const unsigned*)dsm + 6912 + scur * BWORDS;
        #pragma unroll
        for (int ks = 0; ks < 4; ks++) {
            const int kq = ks * 8 + tq;
            LOAD_AFRAGS(Ar);
            #pragma unroll
            for (int in = 0; in < 4; in++) {
                int nc = nbase + in * 8 + grp;
                unsigned p0 = Br[kq * BSTR + nc], p1 = Br[(kq + 4) * BSTR + nc];
                MMA8(c[0][in], a0, p0, p1);
                MMA8(c[1][in], a1, p0, p1);
            }
        }
        scur = (scur == 2) ? 0 : scur + 1;
        spre = (spre == 2) ? 0 : spre + 1;
    }

    #pragma unroll
    for (int im = 0; im < 2; im++)
        #pragma unroll
        for (int in = 0; in < 4; in++)
            #pragma unroll
            for (int r = 0; r < 4; r++) {
                int row = mb + mbase + im * 16 + grp + (r >= 2 ? 8 : 0);
                int col = nb + nbase + in * 8 + 2 * tq + (r & 1);
                out[(size_t)row * D_ + col] += c[im][in][r];
            }
}

// ---- routed stage 1 (dual B, gathered rows) ----
__global__ __launch_bounds__(256, 1) void moe_routed_h_kernel(
    const float* __restrict__ b1, const float* __restrict__ b2)
{
    const int e = blockIdx.z;
    const int cnt = g_cnt[e];
    const int mb = blockIdx.y * BM;
    if (mb >= cnt) return;
    const int nb = blockIdx.x * BN;

    extern __shared__ __align__(16) char dsm[];
    const unsigned smb = (unsigned)__cvta_generic_to_shared(dsm);
    int* slotS = (int*)(dsm + 132096);
    const int tid = threadIdx.x;

    if (tid < BM) {
        int m = mb + tid;
        slotS[tid] = (m < cnt) ? g_slots[e * T_ + m] : g_slots[e * T_];
    }
    __syncthreads();

    const int am = tid >> 2, ac = tid & 3;
    const int bk = tid >> 3, bc = tid & 7;

    const float* aRow = g_xtf + (size_t)(slotS[am] / K_) * D_;
    const float* B1g  = g_w1t + (size_t)e * D_ * I_ + nb;
    const float* B2g  = g_w2t + (size_t)e * D_ * I_ + nb;
    const unsigned aD  = smb + am * 144 + ac * 16;
    const unsigned b1D = smb + 27648 + bk * 544 + bc * 16;
    const unsigned b2D = smb + 79872 + bk * 544 + bc * 16;

    WARP_IDS;

    float c1[2][4][4] = {}, c2[2][4][4] = {};

    #pragma unroll
    for (int s = 0; s < 2; s++) {
        A_COPY(aD + s * ABYTES, aRow, s * BK);
        B_COPY(b1D + s * BBYTES, B1g, I_, s * BK);
        B_COPY(b2D + s * BBYTES, B2g, I_, s * BK);
        CP_COMMIT;
    }

    const int NT = D_ / BK;
    int scur = 0, spre = 2;
    #pragma unroll 1
    for (int kt = 0; kt < NT; kt++) {
        if (kt + 1 < NT) CP_WAIT1; else CP_WAIT0;
        __syncthreads();
        if (kt + 2 < NT) {
            const int k0 = (kt + 2) * BK;
            A_COPY(aD + spre * ABYTES, aRow, k0);
            B_COPY(b1D + spre * BBYTES, B1g, I_, k0);
            B_COPY(b2D + spre * BBYTES, B2g, I_, k0);
            CP_COMMIT;
        }
        const unsigned* Ar  = (const unsigned*)dsm + scur * AWORDS;
        const unsigned* B1r = (const unsigned*)dsm + 6912 + scur * BWORDS;
        const unsigned* B2r = (const unsigned*)dsm + 19968 + scur * BWORDS;
        #pragma unroll
        for (int ks = 0; ks < 4; ks++) {
            const int kq = ks * 8 + tq;
            LOAD_AFRAGS(Ar);
            #pragma unroll
            for (int in = 0; in < 4; in++) {
                int nc = nbase + in * 8 + grp;
                unsigned p0 = B1r[kq * BSTR + nc], p1 = B1r[(kq + 4) * BSTR + nc];
                unsigned q0 = B2r[kq * BSTR + nc], q1 = B2r[(kq + 4) * BSTR + nc];
                MMA8(c1[0][in], a0, p0, p1);
                MMA8(c1[1][in], a1, p0, p1);
                MMA8(c2[0][in], a0, q0, q1);
                MMA8(c2[1][in], a1, q0, q1);
            }
        }
        scur = (scur == 2) ? 0 : scur + 1;
        spre = (spre == 2) ? 0 : spre + 1;
    }

    #pragma unroll
    for (int im = 0; im < 2; im++)
        #pragma unroll
        for (int h = 0; h < 2; h++) {
            int lr = mbase + im * 16 + grp + h * 8;
            bool valid = (mb + lr) < cnt;
            int s = slotS[lr];
            float gv = g_tval[s];
            #pragma unroll
            for (int in = 0; in < 4; in++)
                #pragma unroll
                for (int q2 = 0; q2 < 2; q2++) {
                    int r = h * 2 + q2;
                    int col = nb + nbase + in * 8 + 2 * tq + q2;
                    float h1 = c1[im][in][r] + b1[(size_t)e * I_ + col];
                    float h2 = c2[im][in][r] + b2[(size_t)e * I_ + col];
                    float pp = h1 * h2;
                    float hv = gv * pp / (1.f + expf(-pp));
                    if (valid) g_hs[(size_t)s * I_ + col] = __uint_as_float(f2tf(hv));
                }
        }
}

// ---- routed stage 2: out += g_hs @ W3[e] ----
__global__ __launch_bounds__(256, 2) void moe_routed_out_kernel(float* __restrict__ out)
{
    const int e = blockIdx.z;
    const int cnt = g_cnt[e];
    const int mb = blockIdx.y * BM;
    if (mb >= cnt) return;
    const int nb = blockIdx.x * BN;

    extern __shared__ __align__(16) char dsm[];
    const unsigned smb = (unsigned)__cvta_generic_to_shared(dsm);
    int* slotS = (int*)(dsm + 79872);
    const int tid = threadIdx.x;

    if (tid < BM) {
        int m = mb + tid;
        slotS[tid] = (m < cnt) ? g_slots[e * T_ + m] : g_slots[e * T_];
    }
    __syncthreads();

    const int am = tid >> 2, ac = tid & 3;
    const int bk = tid >> 3, bc = tid & 7;

    const float* aRow = g_hs + (size_t)slotS[am] * I_;
    const float* Bg   = g_w3t + (size_t)e * I_ * D_ + nb;
    const unsigned aD = smb + am * 144 + ac * 16;
    const unsigned bD = smb + 27648 + bk * 544 + bc * 16;

    WARP_IDS;

    float c[2][4][4] = {};

    #pragma unroll
    for (int s = 0; s < 2; s++) {
        A_COPY(aD + s * ABYTES, aRow, s * BK);
        B_COPY(bD + s * BBYTES, Bg, D_, s * BK);
        CP_COMMIT;
    }

    const int NT = I_ / BK;
    int scur = 0, spre = 2;
    #pragma unroll 1
    for (int kt = 0; kt < NT; kt++) {
        if (kt + 1 < NT) CP_WAIT1; else CP_WAIT0;
        __syncthreads();
        if (kt + 2 < NT) {
            const int k0 = (kt + 2) * BK;
            A_COPY(aD + spre * ABYTES, aRow, k0);
            B_COPY(bD + spre * BBYTES, Bg, D_, k0);
            CP_COMMIT;
        }
        const unsigned* Ar = (const unsigned*)dsm + scur * AWORDS;
        const unsigned* Br = (const unsigned*)dsm + 6912 + scur * BWORDS;
        #pragma unroll
        for (int ks = 0; ks < 4; ks++) {
            const int kq = ks * 8 + tq;
            LOAD_AFRAGS(Ar);
            #pragma unroll
            for (int in = 0; in < 4; in++) {
                int nc = nbase + in * 8 + grp;
                unsigned p0 = Br[kq * BSTR + nc], p1 = Br[(kq + 4) * BSTR + nc];
                MMA8(c[0][in], a0, p0, p1);
                MMA8(c[1][in], a1, p0, p1);
            }
        }
        scur = (scur == 2) ? 0 : scur + 1;
        spre = (spre == 2) ? 0 : spre + 1;
    }

    #pragma unroll
    for (int im = 0; im < 2; im++)
        #pragma unroll
        for (int h = 0; h < 2; h++) {
            int lr = mbase + im * 16 + grp + h * 8;
            if ((mb + lr) < cnt) {
                int t = slotS[lr] / K_;
                #pragma unroll
                for (int in = 0; in < 4; in++)
                    #pragma unroll
                    for (int q2 = 0; q2 < 2; q2++) {
                        int col = nb + nbase + in * 8 + 2 * tq + q2;
                        atomicAdd(&out[(size_t)t * D_ + col], c[im][in][h * 2 + q2]);
                    }
            }
        }
}

// ---------------- static init: dynamic-smem opt-in ----------------
namespace {
struct MoeInit {
    MoeInit() {
        cudaFuncSetAttribute(moe_shared_h_kernel,   cudaFuncAttributeMaxDynamicSharedMemorySize, DUAL_SMEM);
        cudaFuncSetAttribute(moe_routed_h_kernel,   cudaFuncAttributeMaxDynamicSharedMemorySize, DUAL_SMEM);
        cudaFuncSetAttribute(moe_out_init_kernel,   cudaFuncAttributeMaxDynamicSharedMemorySize, SINGLE_SMEM);
        cudaFuncSetAttribute(moe_routed_out_kernel, cudaFuncAttributeMaxDynamicSharedMemorySize, SINGLE_SMEM);
    }
};
MoeInit g_moe_init;
}

// ---------------- launch (single stream) ----------------
extern "C" void kernel_launch(void* const* d_in, const int* in_sizes, int n_in,
                              void* d_out, int out_size)
{
    (void)in_sizes; (void)n_in; (void)out_size;
    const float* x   = (const float*)d_in[0];
    const float* rw  = (const float*)d_in[1];
    const float* rb  = (const float*)d_in[2];
    const float* W1  = (const float*)d_in[3];
    const float* b1  = (const float*)d_in[4];
    const float* W2  = (const float*)d_in[5];
    const float* b2  = (const float*)d_in[6];
    const float* W3  = (const float*)d_in[7];
    const float* b3  = (const float*)d_in[8];
    const float* sw1 = (const float*)d_in[9];
    const float* sb1 = (const float*)d_in[10];
    const float* sw2 = (const float*)d_in[11];
    const float* sb2 = (const float*)d_in[12];
    const float* sw3 = (const float*)d_in[13];
    const float* sb3 = (const float*)d_in[14];
    float* out = (float*)d_out;

    moe_init_kernel<<<1, 32>>>();
    moe_cvt_kernel<<<CVT_GRID, 256>>>(W1, W2, W3, sw1, sw2, sw3, x);
    moe_router_kernel<<<T_ / 8, 256>>>(x, rw, rb);
    moe_bias_kernel<<<T_, 256>>>(b3, sb3, out);
    moe_shared_h_kernel<<<dim3(SI_ / BN, T_ / BM), 256, DUAL_SMEM>>>(sb1, sb2);
    moe_out_init_kernel<<<dim3(D_ / BN, T_ / BM), 256, SINGLE_SMEM>>>(out);
    moe_routed_h_kernel<<<dim3(I_ / BN, T_ / BM, E_), 256, DUAL_SMEM>>>(b1, b2);
    moe_routed_out_kernel<<<dim3(D_ / BN, T_ / BM, E_), 256, SINGLE_SMEM>>>(out);
}

// round 10
// speedup vs baseline: 1.0638x; 1.0638x over previous
#include <cuda_runtime.h>
#include <math.h>
#include <stdint.h>

#define T_  2048
#define D_  1024
#define I_  512
#define E_  32
#define K_  6
#define SI_ 1024

#define BM 64
#define BN 128
#define BK 16
#define ASTR 20      // A smem row stride (words), R5-proven conflict-free
#define BSTR 136     // B smem row stride (words), R5-proven conflict-free
#define AW (BM * ASTR)        // 1280 words
#define BW (BK * BSTR)        // 2176 words
#define AB (AW * 4)           // 5120 bytes per A stage
#define BB (BW * 4)           // 8704 bytes per B stage

// 3-stage layouts (words):
//   dual:   A[3]@0 (3840), B1[3]@3840 (6528), B2[3]@10368 (6528) -> 16896 words = 67584 B
//   single: A[3]@0 (3840), B[3]@3840 (6528) -> 10368 words = 41472 B
#define B1W 3840
#define B2W 10368
#define DUAL_SLOTB   67584
#define SINGLE_SLOTB 41472
#define DUAL_SMEM   (DUAL_SLOTB + 256)
#define SINGLE_SMEM (SINGLE_SLOTB + 256)

// ---------------- scratch (no allocations allowed) ----------------
__device__ float g_w1t[E_ * D_ * I_];     // tf32-rounded weights, ORIGINAL layout (R7)
__device__ float g_w2t[E_ * D_ * I_];
__device__ float g_w3t[E_ * I_ * D_];
__device__ float g_sw1t[D_ * SI_];
__device__ float g_sw2t[D_ * SI_];
__device__ float g_sw3t[SI_ * D_];
__device__ float g_xtf[T_ * D_];
__device__ float g_zh[T_ * SI_];
__device__ float g_hs[T_ * K_ * I_];
__device__ int   g_cnt[E_];
__device__ int   g_slots[E_ * T_];
__device__ int   g_tidx[T_ * K_];
__device__ float g_tval[T_ * K_];

__device__ __forceinline__ unsigned f2tf(float f) {
    unsigned u;
    asm("cvt.rna.tf32.f32 %0, %1;" : "=r"(u) : "f"(f));
    return u;
}
__device__ __forceinline__ void cpa16(unsigned dst, const float* src) {
    asm volatile("cp.async.cg.shared.global [%0], [%1], 16;" :: "r"(dst), "l"(src));
}
#define CP_COMMIT asm volatile("cp.async.commit_group;")
#define CP_WAIT1  asm volatile("cp.async.wait_group 1;")
#define CP_WAIT0  asm volatile("cp.async.wait_group 0;")

#define MMA8(c, a, b0v, b1v) \
    asm volatile("mma.sync.aligned.m16n8k8.row.col.f32.tf32.tf32.f32 " \
        "{%0,%1,%2,%3},{%4,%5,%6,%7},{%8,%9},{%0,%1,%2,%3};" \
        : "+f"((c)[0]), "+f"((c)[1]), "+f"((c)[2]), "+f"((c)[3]) \
        : "r"((a)[0]), "r"((a)[1]), "r"((a)[2]), "r"((a)[3]), "r"(b0v), "r"(b1v))

// ---------------- init ----------------
__global__ void moe_init_kernel() {
    if (threadIdx.x < E_) g_cnt[threadIdx.x] = 0;
}

// ---------------- convert weights + x to RNA-rounded tf32 bits (R7-proven) ----------------
__global__ __launch_bounds__(256) void moe_cvt_kernel(
    const float* __restrict__ W1, const float* __restrict__ W2, const float* __restrict__ W3,
    const float* __restrict__ sw1, const float* __restrict__ sw2, const float* __restrict__ sw3,
    const float* __restrict__ x)
{
    const long NW = (long)E_ * D_ * I_ / 4;
    const long NS = (long)D_ * SI_ / 4;
    const long NX = (long)T_ * D_ / 4;
    long i = (long)blockIdx.x * 256 + threadIdx.x;
    const float4* s; float4* d;
    if (i < NW)                     { s = (const float4*)W1  + i;                 d = (float4*)g_w1t  + i; }
    else if (i < 2*NW)              { s = (const float4*)W2  + (i - NW);          d = (float4*)g_w2t  + (i - NW); }
    else if (i < 3*NW)              { s = (const float4*)W3  + (i - 2*NW);        d = (float4*)g_w3t  + (i - 2*NW); }
    else if (i < 3*NW + NS)         { s = (const float4*)sw1 + (i - 3*NW);        d = (float4*)g_sw1t + (i - 3*NW); }
    else if (i < 3*NW + 2*NS)       { s = (const float4*)sw2 + (i - 3*NW - NS);   d = (float4*)g_sw2t + (i - 3*NW - NS); }
    else if (i < 3*NW + 3*NS)       { s = (const float4*)sw3 + (i - 3*NW - 2*NS); d = (float4*)g_sw3t + (i - 3*NW - 2*NS); }
    else if (i < 3*NW + 3*NS + NX)  { s = (const float4*)x   + (i - 3*NW - 3*NS); d = (float4*)g_xtf  + (i - 3*NW - 3*NS); }
    else return;
    float4 v = *s;
    v.x = __uint_as_float(f2tf(v.x)); v.y = __uint_as_float(f2tf(v.y));
    v.z = __uint_as_float(f2tf(v.z)); v.w = __uint_as_float(f2tf(v.w));
    *d = v;
}
#define CVT_GRID 54272

// ---------------- router: 1 warp per token (validated) ----------------
__global__ __launch_bounds__(256) void moe_router_kernel(
    const float* __restrict__ x, const float* __restrict__ rw, const float* __restrict__ rb)
{
    __shared__ float sh[8][32];
    const int wi = threadIdx.x >> 5, lane = threadIdx.x & 31;
    const int t = blockIdx.x * 8 + wi;

    const float4* xr = (const float4*)(x + (size_t)t * D_);
    float4 xv[8];
    #pragma unroll
    for (int d = 0; d < 8; d++) xv[d] = xr[d * 32 + lane];

    for (int e = 0; e < E_; e += 2) {
        const float4* w0 = (const float4*)(rw + (size_t)e * D_);
        const float4* w1 = (const float4*)(rw + (size_t)(e + 1) * D_);
        float acc0 = 0.f, acc1 = 0.f;
        #pragma unroll
        for (int d = 0; d < 8; d++) {
            float4 b0 = w0[d * 32 + lane], b1 = w1[d * 32 + lane];
            acc0 += xv[d].x * b0.x + xv[d].y * b0.y + xv[d].z * b0.z + xv[d].w * b0.w;
            acc1 += xv[d].x * b1.x + xv[d].y * b1.y + xv[d].z * b1.z + xv[d].w * b1.w;
        }
        #pragma unroll
        for (int off = 16; off; off >>= 1) {
            acc0 += __shfl_down_sync(0xffffffffu, acc0, off);
            acc1 += __shfl_down_sync(0xffffffffu, acc1, off);
        }
        if (lane == 0) { sh[wi][e] = acc0 + rb[e]; sh[wi][e + 1] = acc1 + rb[e + 1]; }
    }
    __syncwarp();
    float logit = sh[wi][lane];

    float mx = logit;
    #pragma unroll
    for (int off = 16; off; off >>= 1)
        mx = fmaxf(mx, __shfl_xor_sync(0xffffffffu, mx, off));
    float p = expf(logit - mx);
    float sm = p;
    #pragma unroll
    for (int off = 16; off; off >>= 1)
        sm += __shfl_xor_sync(0xffffffffu, sm, off);
    float score = p / sm;

    const int grp = lane >> 2;
    float v0 = __shfl_sync(0xffffffffu, score, grp * 4 + 0);
    float v1 = __shfl_sync(0xffffffffu, score, grp * 4 + 1);
    float v2 = __shfl_sync(0xffffffffu, score, grp * 4 + 2);
    float v3 = __shfl_sync(0xffffffffu, score, grp * 4 + 3);
    float a = fmaxf(v0, v1), b = fminf(v0, v1);
    float c = fmaxf(v2, v3), dd = fminf(v2, v3);
    float top2 = (a >= c) ? (a + fmaxf(b, c)) : (c + fmaxf(a, dd));

    float gsa[8];
    #pragma unroll
    for (int j = 0; j < 8; j++) gsa[j] = __shfl_sync(0xffffffffu, top2, j * 4);
    unsigned keep = 0;
    #pragma unroll
    for (int it = 0; it < 4; it++) {
        float bv = -1e30f; int bj = 0;
        #pragma unroll
        for (int j = 0; j < 8; j++) {
            bool cand = (((keep >> j) & 1u) == 0u) && (gsa[j] > bv);
            if (cand) { bv = gsa[j]; bj = j; }
        }
        keep |= 1u << bj;
    }

    float msc = ((keep >> grp) & 1u) ? score : -1e30f;
    __syncwarp();
    sh[wi][lane] = msc;
    __syncwarp();

    if (lane == 0) {
        #pragma unroll
        for (int kk = 0; kk < K_; kk++) {
            float bv = -1e30f; int be = 0;
            for (int ee = 0; ee < 32; ee++) {
                float s = sh[wi][ee];
                if (s > bv) { bv = s; be = ee; }
            }
            sh[wi][be] = -2e30f;
            g_tidx[t * K_ + kk] = be;
            g_tval[t * K_ + kk] = bv;
            int pos = atomicAdd(&g_cnt[be], 1);
            g_slots[be * T_ + pos] = t * K_ + kk;
        }
    }
}

// ---------------- bias pre-pass: out[t] = sb3 + sum_k gate_k * b3[e_k] ----------------
__global__ __launch_bounds__(256) void moe_bias_kernel(
    const float* __restrict__ b3, const float* __restrict__ sb3, float* __restrict__ out)
{
    const int t = blockIdx.x;
    int ti[K_]; float tv[K_];
    #pragma unroll
    for (int k = 0; k < K_; k++) { ti[k] = g_tidx[t * K_ + k]; tv[k] = g_tval[t * K_ + k]; }
    for (int n = threadIdx.x * 4; n < D_; n += blockDim.x * 4) {
        float4 v = *(const float4*)(sb3 + n);
        #pragma unroll
        for (int k = 0; k < K_; k++) {
            float4 bb = *(const float4*)(b3 + (size_t)ti[k] * D_ + n);
            v.x = fmaf(tv[k], bb.x, v.x); v.y = fmaf(tv[k], bb.y, v.y);
            v.z = fmaf(tv[k], bb.z, v.z); v.w = fmaf(tv[k], bb.w, v.w);
        }
        *(float4*)(out + (size_t)t * D_ + n) = v;
    }
}

// ======================================================================
// cp.async tf32 GEMMs, BK=16, 3-buffer/2-in-flight, ONE sync per iter:
//   wait_group(1) -> sync -> prefetch(kt+2 -> slot (kt+2)%3) -> compute(slot kt%3)
// Copy + fragment patterns are the R5-proven BK16 set (ASTR=20, BSTR=136).
// ======================================================================

// A copy: thread t -> row am=t>>2, words ac4..ac4+3 (one 16B chunk)
#define A_COPY(dstbase, rowptr, k0)  cpa16((dstbase), (rowptr) + (k0) + ac4)
// B copy: thread t -> k-row bk=t>>4, cols c4b..c4b+3 and c4b+64..c4b+67
#define B_COPY(dstbase, gbase, ldn, k0) do { \
    cpa16((dstbase),       (gbase) + (size_t)((k0) + bk) * (ldn) + c4b); \
    cpa16((dstbase) + 256, (gbase) + (size_t)((k0) + bk) * (ldn) + c4b + 64); \
} while (0)

#define WARP_IDS \
    const int lane = tid & 31, warp = tid >> 5; \
    const int wm = warp >> 2, wn = warp & 3; \
    const int grp = lane >> 2, tq = lane & 3; \
    const int mbase = wm * 32, nbase = wn * 32;

#define LOAD_AFRAGS(Ar) \
    unsigned a0[4], a1[4]; \
    { int r0 = mbase + grp; \
      a0[0] = (Ar)[r0 * ASTR + kq];     a0[1] = (Ar)[(r0 + 8) * ASTR + kq]; \
      a0[2] = (Ar)[r0 * ASTR + kq + 4]; a0[3] = (Ar)[(r0 + 8) * ASTR + kq + 4]; \
      int r1 = r0 + 16; \
      a1[0] = (Ar)[r1 * ASTR + kq];     a1[1] = (Ar)[(r1 + 8) * ASTR + kq]; \
      a1[2] = (Ar)[r1 * ASTR + kq + 4]; a1[3] = (Ar)[(r1 + 8) * ASTR + kq + 4]; }

#define ROT3(v) v = (v == 2) ? 0 : v + 1

// ---- shared stage 1 (dual B): g_zh = tf32(silu((x@sw1+sb1)*(x@sw2+sb2))) ----
__global__ __launch_bounds__(256, 2) void moe_shared_h_kernel(
    const float* __restrict__ sb1, const float* __restrict__ sb2)
{
    extern __shared__ __align__(16) char dsm[];
    const unsigned smb = (unsigned)__cvta_generic_to_shared(dsm);
    const int tid = threadIdx.x;
    const int mb = blockIdx.y * BM, nb = blockIdx.x * BN;
    const int am = tid >> 2, ac4 = (tid & 3) << 2;
    const int bk = tid >> 4, c4b = (tid & 15) << 2;

    const float* aRow = g_xtf + (size_t)(mb + am) * D_;
    const float* B1g  = g_sw1t + nb;
    const float* B2g  = g_sw2t + nb;
    const unsigned aD  = smb + (am * ASTR + ac4) * 4;
    const unsigned b1D = smb + (B1W + bk * BSTR + c4b) * 4;
    const unsigned b2D = smb + (B2W + bk * BSTR + c4b) * 4;

    WARP_IDS;

    float c1[2][4][4] = {}, c2[2][4][4] = {};

    #pragma unroll
    for (int s = 0; s < 2; s++) {
        A_COPY(aD + s * AB, aRow, s * BK);
        B_COPY(b1D + s * BB, B1g, SI_, s * BK);
        B_COPY(b2D + s * BB, B2g, SI_, s * BK);
        CP_COMMIT;
    }

    const int NT = D_ / BK;
    int scur = 0, spre = 2;
    #pragma unroll 1
    for (int kt = 0; kt < NT; kt++) {
        if (kt + 1 < NT) CP_WAIT1; else CP_WAIT0;
        __syncthreads();
        if (kt + 2 < NT) {
            const int k0 = (kt + 2) * BK;
            A_COPY(aD + spre * AB, aRow, k0);
            B_COPY(b1D + spre * BB, B1g, SI_, k0);
            B_COPY(b2D + spre * BB, B2g, SI_, k0);
            CP_COMMIT;
        }
        const unsigned* Ar  = (const unsigned*)dsm + scur * AW;
        const unsigned* B1r = (const unsigned*)dsm + B1W + scur * BW;
        const unsigned* B2r = (const unsigned*)dsm + B2W + scur * BW;
        #pragma unroll
        for (int ks = 0; ks < 2; ks++) {
            const int kq = ks * 8 + tq;
            LOAD_AFRAGS(Ar);
            #pragma unroll
            for (int in = 0; in < 4; in++) {
                int nc = nbase + in * 8 + grp;
                unsigned p0 = B1r[kq * BSTR + nc], p1 = B1r[(kq + 4) * BSTR + nc];
                unsigned q0 = B2r[kq * BSTR + nc], q1 = B2r[(kq + 4) * BSTR + nc];
                MMA8(c1[0][in], a0, p0, p1);
                MMA8(c1[1][in], a1, p0, p1);
                MMA8(c2[0][in], a0, q0, q1);
                MMA8(c2[1][in], a1, q0, q1);
            }
        }
        ROT3(scur); ROT3(spre);
    }

    #pragma unroll
    for (int im = 0; im < 2; im++)
        #pragma unroll
        for (int in = 0; in < 4; in++)
            #pragma unroll
            for (int r = 0; r < 4; r++) {
                int row = mb + mbase + im * 16 + grp + (r >= 2 ? 8 : 0);
                int col = nb + nbase + in * 8 + 2 * tq + (r & 1);
                float h1 = c1[im][in][r] + sb1[col];
                float h2 = c2[im][in][r] + sb2[col];
                float pp = h1 * h2;
                g_zh[(size_t)row * SI_ + col] = __uint_as_float(f2tf(pp / (1.f + expf(-pp))));
            }
}

// ---- shared stage 2: out += g_zh @ sw3 ----
__global__ __launch_bounds__(256, 2) void moe_out_init_kernel(float* __restrict__ out)
{
    extern __shared__ __align__(16) char dsm[];
    const unsigned smb = (unsigned)__cvta_generic_to_shared(dsm);
    const int tid = threadIdx.x;
    const int mb = blockIdx.y * BM, nb = blockIdx.x * BN;
    const int am = tid >> 2, ac4 = (tid & 3) << 2;
    const int bk = tid >> 4, c4b = (tid & 15) << 2;

    const float* aRow = g_zh + (size_t)(mb + am) * SI_;
    const float* Bg   = g_sw3t + nb;
    const unsigned aD = smb + (am * ASTR + ac4) * 4;
    const unsigned bD = smb + (B1W + bk * BSTR + c4b) * 4;

    WARP_IDS;

    float c[2][4][4] = {};

    #pragma unroll
    for (int s = 0; s < 2; s++) {
        A_COPY(aD + s * AB, aRow, s * BK);
        B_COPY(bD + s * BB, Bg, D_, s * BK);
        CP_COMMIT;
    }

    const int NT = SI_ / BK;
    int scur = 0, spre = 2;
    #pragma unroll 1
    for (int kt = 0; kt < NT; kt++) {
        if (kt + 1 < NT) CP_WAIT1; else CP_WAIT0;
        __syncthreads();
        if (kt + 2 < NT) {
            const int k0 = (kt + 2) * BK;
            A_COPY(aD + spre * AB, aRow, k0);
            B_COPY(bD + spre * BB, Bg, D_, k0);
            CP_COMMIT;
        }
        const unsigned* Ar = (const unsigned*)dsm + scur * AW;
        const unsigned* Br = (const unsigned*)dsm + B1W + scur * BW;
        #pragma unroll
        for (int ks = 0; ks < 2; ks++) {
            const int kq = ks * 8 + tq;
            LOAD_AFRAGS(Ar);
            #pragma unroll
            for (int in = 0; in < 4; in++) {
                int nc = nbase + in * 8 + grp;
                unsigned p0 = Br[kq * BSTR + nc], p1 = Br[(kq + 4) * BSTR + nc];
                MMA8(c[0][in], a0, p0, p1);
                MMA8(c[1][in], a1, p0, p1);
            }
        }
        ROT3(scur); ROT3(spre);
    }

    #pragma unroll
    for (int im = 0; im < 2; im++)
        #pragma unroll
        for (int in = 0; in < 4; in++)
            #pragma unroll
            for (int r = 0; r < 4; r++) {
                int row = mb + mbase + im * 16 + grp + (r >= 2 ? 8 : 0);
                int col = nb + nbase + in * 8 + 2 * tq + (r & 1);
                out[(size_t)row * D_ + col] += c[im][in][r];
            }
}

// ---- routed stage 1 (dual B, gathered rows) ----
__global__ __launch_bounds__(256, 2) void moe_routed_h_kernel(
    const float* __restrict__ b1, const float* __restrict__ b2)
{
    const int e = blockIdx.z;
    const int cnt = g_cnt[e];
    const int mb = blockIdx.y * BM;
    if (mb >= cnt) return;
    const int nb = blockIdx.x * BN;

    extern __shared__ __align__(16) char dsm[];
    const unsigned smb = (unsigned)__cvta_generic_to_shared(dsm);
    int* slotS = (int*)(dsm + DUAL_SLOTB);
    const int tid = threadIdx.x;

    if (tid < BM) {
        int m = mb + tid;
        slotS[tid] = (m < cnt) ? g_slots[e * T_ + m] : g_slots[e * T_];
    }
    __syncthreads();

    const int am = tid >> 2, ac4 = (tid & 3) << 2;
    const int bk = tid >> 4, c4b = (tid & 15) << 2;

    const float* aRow = g_xtf + (size_t)(slotS[am] / K_) * D_;
    const float* B1g  = g_w1t + (size_t)e * D_ * I_ + nb;
    const float* B2g  = g_w2t + (size_t)e * D_ * I_ + nb;
    const unsigned aD  = smb + (am * ASTR + ac4) * 4;
    const unsigned b1D = smb + (B1W + bk * BSTR + c4b) * 4;
    const unsigned b2D = smb + (B2W + bk * BSTR + c4b) * 4;

    WARP_IDS;

    float c1[2][4][4] = {}, c2[2][4][4] = {};

    #pragma unroll
    for (int s = 0; s < 2; s++) {
        A_COPY(aD + s * AB, aRow, s * BK);
        B_COPY(b1D + s * BB, B1g, I_, s * BK);
        B_COPY(b2D + s * BB, B2g, I_, s * BK);
        CP_COMMIT;
    }

    const int NT = D_ / BK;
    int scur = 0, spre = 2;
    #pragma unroll 1
    for (int kt = 0; kt < NT; kt++) {
        if (kt + 1 < NT) CP_WAIT1; else CP_WAIT0;
        __syncthreads();
        if (kt + 2 < NT) {
            const int k0 = (kt + 2) * BK;
            A_COPY(aD + spre * AB, aRow, k0);
            B_COPY(b1D + spre * BB, B1g, I_, k0);
            B_COPY(b2D + spre * BB, B2g, I_, k0);
            CP_COMMIT;
        }
        const unsigned* Ar  = (const unsigned*)dsm + scur * AW;
        const unsigned* B1r = (const unsigned*)dsm + B1W + scur * BW;
        const unsigned* B2r = (const unsigned*)dsm + B2W + scur * BW;
        #pragma unroll
        for (int ks = 0; ks < 2; ks++) {
            const int kq = ks * 8 + tq;
            LOAD_AFRAGS(Ar);
            #pragma unroll
            for (int in = 0; in < 4; in++) {
                int nc = nbase + in * 8 + grp;
                unsigned p0 = B1r[kq * BSTR + nc], p1 = B1r[(kq + 4) * BSTR + nc];
                unsigned q0 = B2r[kq * BSTR + nc], q1 = B2r[(kq + 4) * BSTR + nc];
                MMA8(c1[0][in], a0, p0, p1);
                MMA8(c1[1][in], a1, p0, p1);
                MMA8(c2[0][in], a0, q0, q1);
                MMA8(c2[1][in], a1, q0, q1);
            }
        }
        ROT3(scur); ROT3(spre);
    }

    #pragma unroll
    for (int im = 0; im < 2; im++)
        #pragma unroll
        for (int h = 0; h < 2; h++) {
            int lr = mbase + im * 16 + grp + h * 8;
            bool valid = (mb + lr) < cnt;
            int s = slotS[lr];
            float gv = g_tval[s];
            #pragma unroll
            for (int in = 0; in < 4; in++)
                #pragma unroll
                for (int q2 = 0; q2 < 2; q2++) {
                    int r = h * 2 + q2;
                    int col = nb + nbase + in * 8 + 2 * tq + q2;
                    float h1 = c1[im][in][r] + b1[(size_t)e * I_ + col];
                    float h2 = c2[im][in][r] + b2[(size_t)e * I_ + col];
                    float pp = h1 * h2;
                    float hv = gv * pp / (1.f + expf(-pp));
                    if (valid) g_hs[(size_t)s * I_ + col] = __uint_as_float(f2tf(hv));
                }
        }
}

// ---- routed stage 2: out += g_hs @ W3[e] ----
__global__ __launch_bounds__(256, 2) void moe_routed_out_kernel(float* __restrict__ out)
{
    const int e = blockIdx.z;
    const int cnt = g_cnt[e];
    const int mb = blockIdx.y * BM;
    if (mb >= cnt) return;
    const int nb = blockIdx.x * BN;

    extern __shared__ __align__(16) char dsm[];
    const unsigned smb = (unsigned)__cvta_generic_to_shared(dsm);
    int* slotS = (int*)(dsm + SINGLE_SLOTB);
    const int tid = threadIdx.x;

    if (tid < BM) {
        int m = mb + tid;
        slotS[tid] = (m < cnt) ? g_slots[e * T_ + m] : g_slots[e * T_];
    }
    __syncthreads();

    const int am = tid >> 2, ac4 = (tid & 3) << 2;
    const int bk = tid >> 4, c4b = (tid & 15) << 2;

    const float* aRow = g_hs + (size_t)slotS[am] * I_;
    const float* Bg   = g_w3t + (size_t)e * I_ * D_ + nb;
    const unsigned aD = smb + (am * ASTR + ac4) * 4;
    const unsigned bD = smb + (B1W + bk * BSTR + c4b) * 4;

    WARP_IDS;

    float c[2][4][4] = {};

    #pragma unroll
    for (int s = 0; s < 2; s++) {
        A_COPY(aD + s * AB, aRow, s * BK);
        B_COPY(bD + s * BB, Bg, D_, s * BK);
        CP_COMMIT;
    }

    const int NT = I_ / BK;
    int scur = 0, spre = 2;
    #pragma unroll 1
    for (int kt = 0; kt < NT; kt++) {
        if (kt + 1 < NT) CP_WAIT1; else CP_WAIT0;
        __syncthreads();
        if (kt + 2 < NT) {
            const int k0 = (kt + 2) * BK;
            A_COPY(aD + spre * AB, aRow, k0);
            B_COPY(bD + spre * BB, Bg, D_, k0);
            CP_COMMIT;
        }
        const unsigned* Ar = (const unsigned*)dsm + scur * AW;
        const unsigned* Br = (const unsigned*)dsm + B1W + scur * BW;
        #pragma unroll
        for (int ks = 0; ks < 2; ks++) {
            const int kq = ks * 8 + tq;
            LOAD_AFRAGS(Ar);
            #pragma unroll
            for (int in = 0; in < 4; in++) {
                int nc = nbase + in * 8 + grp;
                unsigned p0 = Br[kq * BSTR + nc], p1 = Br[(kq + 4) * BSTR + nc];
                MMA8(c[0][in], a0, p0, p1);
                MMA8(c[1][in], a1, p0, p1);
            }
        }
        ROT3(scur); ROT3(spre);
    }

    #pragma unroll
    for (int im = 0; im < 2; im++)
        #pragma unroll
        for (int h = 0; h < 2; h++) {
            int lr = mbase + im * 16 + grp + h * 8;
            if ((mb + lr) < cnt) {
                int t = slotS[lr] / K_;
                #pragma unroll
                for (int in = 0; in < 4; in++)
                    #pragma unroll
                    for (int q2 = 0; q2 < 2; q2++) {
                        int col = nb + nbase + in * 8 + 2 * tq + q2;
                        atomicAdd(&out[(size_t)t * D_ + col], c[im][in][h * 2 + q2]);
                    }
            }
        }
}

// ---------------- static init: dynamic-smem opt-in ----------------
namespace {
struct MoeInit {
    MoeInit() {
        cudaFuncSetAttribute(moe_shared_h_kernel,   cudaFuncAttributeMaxDynamicSharedMemorySize, DUAL_SMEM);
        cudaFuncSetAttribute(moe_routed_h_kernel,   cudaFuncAttributeMaxDynamicSharedMemorySize, DUAL_SMEM);
        cudaFuncSetAttribute(moe_out_init_kernel,   cudaFuncAttributeMaxDynamicSharedMemorySize, SINGLE_SMEM);
        cudaFuncSetAttribute(moe_routed_out_kernel, cudaFuncAttributeMaxDynamicSharedMemorySize, SINGLE_SMEM);
    }
};
MoeInit g_moe_init;
}

// ---------------- launch (single stream) ----------------
extern "C" void kernel_launch(void* const* d_in, const int* in_sizes, int n_in,
                              void* d_out, int out_size)
{
    (void)in_sizes; (void)n_in; (void)out_size;
    const float* x   = (const float*)d_in[0];
    const float* rw  = (const float*)d_in[1];
    const float* rb  = (const float*)d_in[2];
    const float* W1  = (const float*)d_in[3];
    const float* b1  = (const float*)d_in[4];
    const float* W2  = (const float*)d_in[5];
    const float* b2  = (const float*)d_in[6];
    const float* W3  = (const float*)d_in[7];
    const float* b3  = (const float*)d_in[8];
    const float* sw1 = (const float*)d_in[9];
    const float* sb1 = (const float*)d_in[10];
    const float* sw2 = (const float*)d_in[11];
    const float* sb2 = (const float*)d_in[12];
    const float* sw3 = (const float*)d_in[13];
    const float* sb3 = (const float*)d_in[14];
    float* out = (float*)d_out;

    moe_init_kernel<<<1, 32>>>();
    moe_cvt_kernel<<<CVT_GRID, 256>>>(W1, W2, W3, sw1, sw2, sw3, x);
    moe_router_kernel<<<T_ / 8, 256>>>(x, rw, rb);
    moe_bias_kernel<<<T_, 256>>>(b3, sb3, out);
    moe_shared_h_kernel<<<dim3(SI_ / BN, T_ / BM), 256, DUAL_SMEM>>>(sb1, sb2);
    moe_out_init_kernel<<<dim3(D_ / BN, T_ / BM), 256, SINGLE_SMEM>>>(out);
    moe_routed_h_kernel<<<dim3(I_ / BN, T_ / BM, E_), 256, DUAL_SMEM>>>(b1, b2);
    moe_routed_out_kernel<<<dim3(D_ / BN, T_ / BM, E_), 256, SINGLE_SMEM>>>(out);
}